// round 5
// baseline (speedup 1.0000x reference)
#include <cuda_runtime.h>
#include <cstdint>

// Problem constants: SUPPORT=(16,16), N_NODES=100000, F=64, B=4096
#define BATCH_N    4096
#define SUP        16
#define FDIM       64
#define ROW_LEN    65          // 1 weight col + 64 features
#define ROWS_PER_B 1088        // 2 * 16 * 34
#define GROUP_ROWS 34          // 2 + 2*16
#define N_GROUPS   (BATCH_N * 2 * SUP)        // 131072 groups
#define GROUPS_PER_BLOCK 4
#define CHUNK_ROWS   (GROUPS_PER_BLOCK * GROUP_ROWS)   // 136
#define CHUNK_FLOATS (CHUNK_ROWS * ROW_LEN)            // 8840 floats = 35360 B (16B aligned!)
#define THREADS    256
#define N_BLOCKS   (N_GROUPS / GROUPS_PER_BLOCK)       // 32768

__global__ __launch_bounds__(THREADS)
void gae_gather_stage_kernel(const int*   __restrict__ node_ids,
                             const float* __restrict__ features,
                             const int*   __restrict__ in_sample,
                             const int*   __restrict__ out_sample,
                             const float* __restrict__ in_amnt,
                             const float* __restrict__ out_amnt,
                             float*       __restrict__ feat_out,
                             float*       __restrict__ w_out) {
    __shared__ float buf[CHUNK_FLOATS];     // staged feat rows, output layout
    __shared__ float wbuf[CHUNK_ROWS];      // staged weights

    const int lane = threadIdx.x & 31;
    const int warp = threadIdx.x >> 5;      // 0..7
    const int g0   = blockIdx.x * GROUPS_PER_BLOCK;

    // All 4 groups of this chunk belong to the same batch element b
    // (32 groups per b, g0 is a multiple of 4).
    const int b = g0 >> 5;
    const int n = node_ids[b];

    // ---- Fill phase: each warp owns rows r = warp + 8k, k = 0..16 ----
    #pragma unroll 4
    for (int k = 0; k < 17; k++) {
        const int r   = warp + (k << 3);         // 0..135
        const int grp = r / GROUP_ROWS;
        const int rr  = r - grp * GROUP_ROWS;    // 0..33
        const int g   = g0 + grp;
        const int rem = g & 31;
        const int half = rem >> 4;               // 0=in-branch hop1, 1=out-branch
        const int i    = rem & 15;

        const int*   s1 = half ? out_sample : in_sample;
        const float* a1 = half ? out_amnt  : in_amnt;
        const int   n1 = s1[n * SUP + i];
        const float w1 = a1[n * SUP + i];

        int m; float c0, wv;
        if (rr == 0 || rr == 17) {
            m = n1;  c0 = w1;  wv = w1 * w1;
        } else if (rr <= 16) {
            m  = in_sample[n1 * SUP + (rr - 1)];
            c0 = in_amnt  [n1 * SUP + (rr - 1)];
            wv = c0 * w1;
        } else {
            m  = out_sample[n1 * SUP + (rr - 18)];
            c0 = out_amnt  [n1 * SUP + (rr - 18)];
            wv = c0 * w1;
        }

        // Coalesced 256B feature-row gather (L2-resident table).
        const float* src = features + (size_t)m * FDIM;
        const float v0 = src[lane];
        const float v1 = src[lane + 32];

        float* row = buf + r * ROW_LEN;
        if (lane == 0) { row[0] = c0; wbuf[r] = wv; }
        row[1 + lane]  = v0;     // cols 1..32  (feat 0..31), stride-1 -> conflict-free
        row[33 + lane] = v1;     // cols 33..64 (feat 32..63)
    }
    __syncthreads();

    // ---- Copy-out phase: aligned float4 streaming stores ----
    {
        const float4* sb   = (const float4*)buf;
        float4* dst = (float4*)(feat_out + (size_t)g0 * GROUP_ROWS * ROW_LEN);
        #pragma unroll
        for (int t = threadIdx.x; t < CHUNK_FLOATS / 4; t += THREADS) {
            __stcs(dst + t, sb[t]);          // evict-first: protect L2-resident tables
        }
        // Weights: 136 floats = 34 float4, chunk base is 16B aligned.
        const float4* swb = (const float4*)wbuf;
        float4* wdst = (float4*)(w_out + (size_t)g0 * GROUP_ROWS);
        if (threadIdx.x < CHUNK_ROWS / 4) {
            __stcs(wdst + threadIdx.x, swb[threadIdx.x]);
        }
    }
}

extern "C" void kernel_launch(void* const* d_in, const int* in_sizes, int n_in,
                              void* d_out, int out_size) {
    const int*   node_ids = (const int*)  d_in[0];
    const float* features = (const float*)d_in[1];
    const int*   in_samp  = (const int*)  d_in[2];
    const int*   out_samp = (const int*)  d_in[3];
    const float* in_amnt  = (const float*)d_in[4];
    const float* out_amnt = (const float*)d_in[5];

    float* feat_out = (float*)d_out;
    float* w_out    = feat_out + (size_t)BATCH_N * ROWS_PER_B * ROW_LEN;

    gae_gather_stage_kernel<<<N_BLOCKS, THREADS>>>(node_ids, features, in_samp, out_samp,
                                                   in_amnt, out_amnt, feat_out, w_out);
}

// round 6
// speedup vs baseline: 1.7615x; 1.7615x over previous
#include <cuda_runtime.h>
#include <cstdint>

// Problem constants: SUPPORT=(16,16), N_NODES=100000, F=64, B=4096
#define BATCH_N    4096
#define SUP        16
#define FDIM       64
#define ROW_LEN    65          // 1 weight col + 64 features
#define ROWS_PER_B 1088        // 2 * 16 * 34
#define GROUP_ROWS 34          // 2 + 2*16
#define N_GROUPS   (BATCH_N * 2 * SUP)   // 131072 warps
#define WARPS_PER_BLOCK 8
#define THREADS (WARPS_PER_BLOCK * 32)

__global__ __launch_bounds__(THREADS)
void gae_gather_align_kernel(const int*   __restrict__ node_ids,
                             const float* __restrict__ features,
                             const int*   __restrict__ in_sample,
                             const int*   __restrict__ out_sample,
                             const float* __restrict__ in_amnt,
                             const float* __restrict__ out_amnt,
                             float*       __restrict__ feat_out,
                             float*       __restrict__ w_out) {
    const int warp_in_block = threadIdx.x >> 5;
    const int lane = threadIdx.x & 31;
    const int g = blockIdx.x * WARPS_PER_BLOCK + warp_in_block;
    if (g >= N_GROUPS) return;

    const int b    = g >> 5;        // 32 groups per batch element
    const int rem  = g & 31;
    const int half = rem >> 4;      // 0 = in-branch at hop1, 1 = out-branch
    const int i    = rem & 15;      // first-hop neighbor index

    const int n = node_ids[b];
    const int*   s1 = half ? out_sample : in_sample;
    const float* a1 = half ? out_amnt  : in_amnt;
    const int   n1 = s1[n * SUP + i];
    const float w1 = a1[n * SUP + i];

    // Per-lane precompute of (node, scalar) for row r = lane (0..31).
    int   mA;  float sA;
    {
        const int r = lane;
        if (r == 0 || r == 17) { mA = n1; sA = w1; }
        else if (r <= 16)      { mA = in_sample [n1 * SUP + (r - 1)];
                                 sA = in_amnt   [n1 * SUP + (r - 1)]; }
        else                   { mA = out_sample[n1 * SUP + (r - 18)];
                                 sA = out_amnt  [n1 * SUP + (r - 18)]; }
    }
    // Rows 32,33 (j = 14,15 of the out-branch) on lanes 0,1.
    int mB = 0; float sB = 0.f;
    if (lane < 2) {
        mB = out_sample[n1 * SUP + (14 + lane)];
        sB = out_amnt  [n1 * SUP + (14 + lane)];
    }

    const size_t rowbase = (size_t)b * ROWS_PER_B + (size_t)half * 544 + (size_t)i * GROUP_ROWS;

    // Weight output: w1^2 for self-rows, w2*w1 otherwise.
    {
        const float wv = (lane == 0 || lane == 17) ? (w1 * w1) : (sA * w1);
        w_out[rowbase + lane] = wv;
        if (lane < 2) w_out[rowbase + 32 + lane] = sB * w1;
    }

    // Feature rows: broadcast (m, s), gather 256B feature row coalesced,
    // realign with 2 shuffles, emit 3 perfectly line-aligned 128B stores.
    size_t fb = rowbase * (size_t)ROW_LEN;   // flat float index of row start
    #pragma unroll 2
    for (int rr = 0; rr < GROUP_ROWS; rr++, fb += ROW_LEN) {
        int m; float s;
        if (rr < 32) {
            m = __shfl_sync(0xffffffffu, mA, rr);
            s = __shfl_sync(0xffffffffu, sA, rr);
        } else {
            m = __shfl_sync(0xffffffffu, mB, rr - 32);
            s = __shfl_sync(0xffffffffu, sB, rr - 32);
        }
        const float* src = features + (size_t)m * FDIM;
        const float v0 = src[lane];          // feats 0..31  (1 wavefront, 128B aligned)
        const float v1 = src[lane + 32];     // feats 32..63 (1 wavefront)

        const int a = (int)(fb & 31);                 // misalignment in floats
        const int k = (lane - a - 1) & 31;            // shared shuffle index
        const float fv0 = __shfl_sync(0xffffffffu, v0, k);
        const float fv1 = __shfl_sync(0xffffffffu, v1, k);

        float* basep = feat_out + (fb - a);           // 128B-aligned chunk base

        // chunk 0: elements e = lane - a, active for lane >= a (1 wavefront)
        if (lane >= a) basep[lane] = (lane == a) ? s : fv0;
        // chunk 1: e = lane + 32 - a, always in-row (1 wavefront)
        basep[lane + 32] = (lane + 32 - a <= 32) ? fv0 : fv1;
        // chunk 2: e = lane + 64 - a <= 64, active for lane <= a (1 wavefront)
        if (lane <= a) basep[lane + 64] = fv1;
    }
}

extern "C" void kernel_launch(void* const* d_in, const int* in_sizes, int n_in,
                              void* d_out, int out_size) {
    const int*   node_ids = (const int*)  d_in[0];
    const float* features = (const float*)d_in[1];
    const int*   in_samp  = (const int*)  d_in[2];
    const int*   out_samp = (const int*)  d_in[3];
    const float* in_amnt  = (const float*)d_in[4];
    const float* out_amnt = (const float*)d_in[5];

    float* feat_out = (float*)d_out;
    float* w_out    = feat_out + (size_t)BATCH_N * ROWS_PER_B * ROW_LEN;

    const int blocks = N_GROUPS / WARPS_PER_BLOCK;   // 16384
    gae_gather_align_kernel<<<blocks, THREADS>>>(node_ids, features, in_samp, out_samp,
                                                 in_amnt, out_amnt, feat_out, w_out);
}

// round 7
// speedup vs baseline: 1.9075x; 1.0829x over previous
#include <cuda_runtime.h>
#include <cstdint>

// Problem constants: SUPPORT=(16,16), N_NODES=100000, F=64, B=4096
#define BATCH_N    4096
#define SUP        16
#define FDIM       64
#define ROW_LEN    65          // 1 weight col + 64 features
#define ROWS_PER_B 1088        // 2 * 16 * 34
#define GROUP_ROWS 34          // 2 + 2*16
#define N_GROUPS   (BATCH_N * 2 * SUP)   // 131072 warps
#define WARPS_PER_BLOCK 8
#define THREADS (WARPS_PER_BLOCK * 32)

__global__ __launch_bounds__(THREADS)
void gae_gather_rot_kernel(const int*   __restrict__ node_ids,
                           const float* __restrict__ features,
                           const int*   __restrict__ in_sample,
                           const int*   __restrict__ out_sample,
                           const float* __restrict__ in_amnt,
                           const float* __restrict__ out_amnt,
                           float*       __restrict__ feat_out,
                           float*       __restrict__ w_out) {
    const int warp_in_block = threadIdx.x >> 5;
    const int lane = threadIdx.x & 31;
    const int g = blockIdx.x * WARPS_PER_BLOCK + warp_in_block;
    if (g >= N_GROUPS) return;

    const int b    = g >> 5;        // 32 groups per batch element
    const int rem  = g & 31;
    const int half = rem >> 4;      // 0 = in-branch at hop1, 1 = out-branch
    const int i    = rem & 15;      // first-hop neighbor index

    const int n = node_ids[b];
    const int*   s1 = half ? out_sample : in_sample;
    const float* a1 = half ? out_amnt  : in_amnt;
    const int   n1 = s1[n * SUP + i];
    const float w1 = a1[n * SUP + i];

    // Per-lane precompute of (node, scalar) for row r = lane (0..31).
    int   mA;  float sA;
    {
        const int r = lane;
        if (r == 0 || r == 17) { mA = n1; sA = w1; }
        else if (r <= 16)      { mA = in_sample [n1 * SUP + (r - 1)];
                                 sA = in_amnt   [n1 * SUP + (r - 1)]; }
        else                   { mA = out_sample[n1 * SUP + (r - 18)];
                                 sA = out_amnt  [n1 * SUP + (r - 18)]; }
    }
    // Rows 32,33 (j = 14,15 of the out-branch) on lanes 0,1.
    int mB = 0; float sB = 0.f;
    if (lane < 2) {
        mB = out_sample[n1 * SUP + (14 + lane)];
        sB = out_amnt  [n1 * SUP + (14 + lane)];
    }

    const size_t rowbase = (size_t)b * ROWS_PER_B + (size_t)half * 544 + (size_t)i * GROUP_ROWS;

    // Weight output: w1^2 for self-rows, w2*w1 otherwise. Streaming stores.
    {
        const float wv = (lane == 0 || lane == 17) ? (w1 * w1) : (sA * w1);
        __stcs(&w_out[rowbase + lane], wv);
        if (lane < 2) __stcs(&w_out[rowbase + 32 + lane], sB * w1);
    }

    // Feature rows: broadcast (m, s); ROTATED coalesced loads (permuted within
    // the 128B line -> still 1 wavefront, no realign shuffle needed); three
    // line-aligned streaming stores.
    size_t fb = rowbase * (size_t)ROW_LEN;   // flat float index of row start
    #pragma unroll 4
    for (int rr = 0; rr < GROUP_ROWS; rr++, fb += ROW_LEN) {
        int m; float s;
        if (rr < 32) {
            m = __shfl_sync(0xffffffffu, mA, rr);
            s = __shfl_sync(0xffffffffu, sA, rr);
        } else {
            m = __shfl_sync(0xffffffffu, mB, rr - 32);
            s = __shfl_sync(0xffffffffu, sB, rr - 32);
        }
        const int a = (int)(fb & 31);                 // misalignment in floats
        const int k = (lane - a - 1) & 31;            // rotated lane index

        const float* src = features + (size_t)m * FDIM;
        const float v0 = __ldg(src + k);              // feats 0..31, permuted (1 wf)
        const float v1 = __ldg(src + k + 32);         // feats 32..63, permuted (1 wf)

        float* basep = feat_out + (fb - a);           // 128B-aligned chunk base

        // chunk 0: e = lane - a (active lane >= a): e==0 -> scalar, else f[e-1]=v0
        if (lane >= a) __stcs(&basep[lane], (lane == a) ? s : v0);
        // chunk 1: e = lane + 32 - a: e<=32 -> f[e-1]=v0 else v1
        __stcs(&basep[lane + 32], (lane <= a) ? v0 : v1);
        // chunk 2: e = lane + 64 - a <= 64 (active lane <= a): f[e-1]=v1
        if (lane <= a) __stcs(&basep[lane + 64], v1);
    }
}

extern "C" void kernel_launch(void* const* d_in, const int* in_sizes, int n_in,
                              void* d_out, int out_size) {
    const int*   node_ids = (const int*)  d_in[0];
    const float* features = (const float*)d_in[1];
    const int*   in_samp  = (const int*)  d_in[2];
    const int*   out_samp = (const int*)  d_in[3];
    const float* in_amnt  = (const float*)d_in[4];
    const float* out_amnt = (const float*)d_in[5];

    float* feat_out = (float*)d_out;
    float* w_out    = feat_out + (size_t)BATCH_N * ROWS_PER_B * ROW_LEN;

    const int blocks = N_GROUPS / WARPS_PER_BLOCK;   // 16384
    gae_gather_rot_kernel<<<blocks, THREADS>>>(node_ids, features, in_samp, out_samp,
                                               in_amnt, out_amnt, feat_out, w_out);
}